// round 16
// baseline (speedup 1.0000x reference)
#include <cuda_runtime.h>
#include <cstdint>
#include <cstddef>

// Problem shapes (fixed)
#define BB   32
#define TT   8192
#define QD   512
#define VD   256
#define DD   128
#define TILE_T 256           // t-rows per score tile (2 x 128-row MMA accumulators)
#define KCH    32            // k-floats per SMEM chunk (= 128B = one SW128 atom row)
#define NCHUNK (VD / KCH)    // 8
#define STAGE_BYTES (3 * 16384)   // A0 + A1 + B per stage

#if defined(__CUDA_ARCH__) && (defined(__CUDA_ARCH_FEAT_SM103_ALL) || \
                               defined(__CUDA_ARCH_FEAT_SM100_ALL) || \
                               defined(__CUDA_ARCH_SPECIFIC__)     || \
                               defined(__CUDA_ARCH_FAMILY_SPECIFIC__))
#define HAS_TCGEN05 1
#else
#define HAS_TCGEN05 0
#endif

// ---------------- device scratch (no allocation allowed) ----------------
__device__ float g_q[BB * DD];
__device__ float g_WvT[DD * VD];        // Wv transposed: [d][k]
__device__ float g_score[BB * TT];
__device__ __align__(16) float g_Spart[16][BB][VD];
__device__ float g_sumA[BB];

// ---------------- generic PTX helpers ----------------
__device__ __forceinline__ uint32_t smem_u32(const void* p) {
    uint32_t a;
    asm("{ .reg .u64 t; cvta.to.shared.u64 t, %1; cvt.u32.u64 %0, t; }" : "=r"(a) : "l"(p));
    return a;
}
__device__ __forceinline__ uint32_t elect_one_pred() {
    uint32_t p;
    asm volatile("{\n\t.reg .pred p;\n\telect.sync _|p, 0xFFFFFFFF;\n\tselp.b32 %0, 1, 0, p;\n\t}" : "=r"(p));
    return p;
}
__device__ __forceinline__ float tanh_fast(float x) {
    float y;
    asm("tanh.approx.f32 %0, %1;" : "=f"(y) : "f"(x));
    return y;
}

#define CP_ASYNC16(dst_u32, src_ptr) \
    asm volatile("cp.async.cg.shared.global [%0], [%1], 16;" \
                 :: "r"(dst_u32), "l"(src_ptr) : "memory")
#define CP_ASYNC_COMMIT() asm volatile("cp.async.commit_group;" ::: "memory")
#define CP_ASYNC_WAIT(n)  asm volatile("cp.async.wait_group %0;" :: "n"(n) : "memory")

#define MBARRIER_INIT(addr, cnt) \
    asm volatile("mbarrier.init.shared.b64 [%0], %1;" :: "r"(addr), "r"(cnt) : "memory")

#define MBARRIER_WAIT_PARITY(mbar, parity) do {                                   \
    uint32_t _m = (mbar); uint32_t _p = (parity); uint32_t _d;                    \
    asm volatile("{\n\t.reg .pred p;\n\t"                                         \
        "mbarrier.try_wait.parity.acquire.cta.shared::cta.b64 p, [%1], %2;\n\t"   \
        "selp.b32 %0, 1, 0, p;\n\t}" : "=r"(_d) : "r"(_m), "r"(_p) : "memory");   \
    if (!_d) {                                                                    \
        asm volatile("{\n\t.reg .pred P1;\n\t"                                    \
            "WL_%=:\n\t"                                                          \
            "mbarrier.try_wait.parity.acquire.cta.shared::cta.b64 P1, [%0], %1, 0x989680;\n\t" \
            "@P1 bra.uni WD_%=;\n\t"                                              \
            "bra.uni WL_%=;\n\t"                                                  \
            "WD_%=:\n\t}" :: "r"(_m), "r"(_p) : "memory");                        \
    }                                                                             \
} while (0)

// ---------------- tcgen05 helpers ----------------
#define TCGEN05_ALLOC(res_addr, ncols) \
    asm volatile("tcgen05.alloc.cta_group::1.sync.aligned.shared::cta.b32 [%0], %1;" \
                 :: "r"(res_addr), "r"((uint32_t)(ncols)) : "memory")
#define TCGEN05_RELINQ() \
    asm volatile("tcgen05.relinquish_alloc_permit.cta_group::1.sync.aligned;")
#define TCGEN05_DEALLOC(tmem, ncols) \
    asm volatile("tcgen05.dealloc.cta_group::1.sync.aligned.b32 %0, %1;" :: "r"(tmem), "r"((uint32_t)(ncols)))
#define TCGEN05_COMMIT(mbar) \
    asm volatile("tcgen05.commit.cta_group::1.mbarrier::arrive::one.shared::cluster.b64 [%0];" \
                 :: "r"(mbar) : "memory")
#define TCGEN05_FENCE_AFTER() \
    asm volatile("tcgen05.fence::after_thread_sync;" ::: "memory")
#define TCGEN05_WAIT_LD() \
    asm volatile("tcgen05.wait::ld.sync.aligned;" ::: "memory")
#define FENCE_PROXY_ASYNC() \
    asm volatile("fence.proxy.async.shared::cta;" ::: "memory")

#define TCGEN05_LD_X32(r, tmem_addr)                                              \
    asm volatile("tcgen05.ld.sync.aligned.32x32b.x32.b32 "                        \
        "{%0, %1, %2, %3, %4, %5, %6, %7, "                                       \
        " %8, %9, %10, %11, %12, %13, %14, %15, "                                 \
        " %16, %17, %18, %19, %20, %21, %22, %23, "                               \
        " %24, %25, %26, %27, %28, %29, %30, %31}, [%32];"                        \
        : "=r"((r)[0]),  "=r"((r)[1]),  "=r"((r)[2]),  "=r"((r)[3]),              \
          "=r"((r)[4]),  "=r"((r)[5]),  "=r"((r)[6]),  "=r"((r)[7]),              \
          "=r"((r)[8]),  "=r"((r)[9]),  "=r"((r)[10]), "=r"((r)[11]),             \
          "=r"((r)[12]), "=r"((r)[13]), "=r"((r)[14]), "=r"((r)[15]),             \
          "=r"((r)[16]), "=r"((r)[17]), "=r"((r)[18]), "=r"((r)[19]),             \
          "=r"((r)[20]), "=r"((r)[21]), "=r"((r)[22]), "=r"((r)[23]),             \
          "=r"((r)[24]), "=r"((r)[25]), "=r"((r)[26]), "=r"((r)[27]),             \
          "=r"((r)[28]), "=r"((r)[29]), "=r"((r)[30]), "=r"((r)[31])              \
        : "r"(tmem_addr))

// SW128 K-major SMEM descriptor (LBO=1, SBO=64, version=1, layout=SW128)
static __device__ constexpr uint64_t SMEM_DESC_BASE_SW128 =
    (uint64_t(2) << 61) | (uint64_t(1) << 46) | (uint64_t(64) << 32) | (uint64_t(1) << 16);
__device__ __forceinline__ uint64_t make_desc(uint32_t addr) {
    return SMEM_DESC_BASE_SW128 | ((uint64_t)(addr >> 4) & 0x3FFF);
}

#if HAS_TCGEN05
__device__ __forceinline__ void mma_tf32_ss(uint32_t d_tmem, uint64_t a_desc, uint64_t b_desc,
                                            uint32_t idesc, uint32_t enable) {
    asm volatile(
        "{\n\t.reg .pred p;\n\t"
        "setp.ne.u32 p, %4, 0;\n\t"
        "tcgen05.mma.cta_group::1.kind::tf32 [%0], %1, %2, %3, {%5, %5, %5, %5}, p;\n\t}"
        :: "r"(d_tmem), "l"(a_desc), "l"(b_desc), "r"(idesc), "r"(enable), "r"(0u)
        : "memory");
}
#endif

// ---------------- f32x2 packed-FMA helpers (fallback path) ----------------
__device__ __forceinline__ unsigned long long pack2(float lo, float hi) {
    unsigned long long r;
    asm("mov.b64 %0, {%1, %2};" : "=l"(r) : "f"(lo), "f"(hi));
    return r;
}
__device__ __forceinline__ void unpack2(unsigned long long v, float& lo, float& hi) {
    asm("mov.b64 {%0, %1}, %2;" : "=f"(lo), "=f"(hi) : "l"(v));
}
__device__ __forceinline__ void ffma2(unsigned long long& d,
                                      unsigned long long a,
                                      unsigned long long b) {
    asm("fma.rn.f32x2 %0, %1, %2, %0;" : "+l"(d) : "l"(a), "l"(b));
}

// ---------------- merged setup: qproj (blocks 0-31) + WvT transpose (32-63) + zero (64) ----------------
__global__ __launch_bounds__(512) void setup_kernel(const float* __restrict__ query,
                                                    const float* __restrict__ Wq,
                                                    const float* __restrict__ bq,
                                                    const float* __restrict__ Wv) {
    __shared__ float part[4][DD];
    __shared__ float tile[32][33];
    int blk = blockIdx.x;
    int tid = threadIdx.x;

    if (blk < BB) {
        int b  = blk;
        int d  = tid & 127;
        int sl = tid >> 7;
        const float* qr = query + (size_t)b * QD + sl * 128;
        const float* wq = Wq + (size_t)sl * 128 * DD + d;
        float a0 = 0.f, a1 = 0.f, a2 = 0.f, a3 = 0.f;
#pragma unroll 8
        for (int k = 0; k < 128; k += 4) {
            a0 += qr[k + 0] * wq[(size_t)(k + 0) * DD];
            a1 += qr[k + 1] * wq[(size_t)(k + 1) * DD];
            a2 += qr[k + 2] * wq[(size_t)(k + 2) * DD];
            a3 += qr[k + 3] * wq[(size_t)(k + 3) * DD];
        }
        part[sl][d] = (a0 + a1) + (a2 + a3);
        __syncthreads();
        if (sl == 0)
            g_q[b * DD + d] = bq[d] + (part[0][d] + part[1][d]) + (part[2][d] + part[3][d]);
    } else if (blk < 2 * BB) {
        int idx = blk - BB;
        int k0 = (idx & 7) * 32;
        int d0 = (idx >> 3) * 32;
        int tx = tid & 31, ty = tid >> 5;
#pragma unroll
        for (int r = 0; r < 2; r++)
            tile[ty + r * 16][tx] = Wv[(size_t)(k0 + ty + r * 16) * DD + d0 + tx];
        __syncthreads();
#pragma unroll
        for (int r = 0; r < 2; r++)
            g_WvT[(size_t)(d0 + ty + r * 16) * VD + k0 + tx] = tile[tx][ty + r * 16];
    } else {
        if (tid < BB) g_sumA[tid] = 0.f;
    }
}

// ---------------- kernel B: score GEMM + Bahdanau epilogue (R10/R14 structure) ----------------
__global__ __launch_bounds__(256) void score_kernel(
    const float* __restrict__ value,
    const float* __restrict__ Wv,
    const float* __restrict__ bv,
    const float* __restrict__ av,
    const float* __restrict__ sbias) {

#if HAS_TCGEN05
    extern __shared__ char dynraw[];
    __shared__ uint32_t s_tmem[1];
    __shared__ __align__(8) unsigned long long s_mbar[2];
    __shared__ float qsh[DD], avsh[DD];

    char* dbase = (char*)(((uintptr_t)dynraw + 1023) & ~(uintptr_t)1023);

    int tid = threadIdx.x;
    int wid = tid >> 5, lid = tid & 31;
    int b = blockIdx.y, t0 = blockIdx.x * TILE_T;

    uint32_t mbar0 = smem_u32(&s_mbar[0]);
    uint32_t mbar1 = smem_u32(&s_mbar[1]);
    uint32_t tptr_u32 = smem_u32(&s_tmem[0]);
    uint32_t stage_u32[2] = { smem_u32(dbase), smem_u32(dbase + STAGE_BYTES) };

    const float* vrow = value + ((size_t)b * TT + t0) * VD;
    const float* wrow = g_WvT;

    // Per-thread copy slots: 8 A-slots (value rows 0..255) + 4 B-slots (WvT rows 0..127).
    uint32_t adst[8], bdst[4];
    const float* asrc[8];
    const float* bsrc[4];
#pragma unroll
    for (int i = 0; i < 8; i++) {
        int j = i * 256 + tid;
        int row = j >> 3;
        uint32_t off = (row & 127) * 128 + (j & 7) * 16;
        uint32_t sw = off ^ ((off >> 3) & 0x70);
        adst[i] = ((row >> 7) ? 16384u : 0u) + sw;
        asrc[i] = vrow + (size_t)row * VD + (j & 7) * 4;
    }
#pragma unroll
    for (int i = 0; i < 4; i++) {
        int j = i * 256 + tid;
        int row = j >> 3;
        uint32_t off = row * 128 + (j & 7) * 16;
        uint32_t sw = off ^ ((off >> 3) & 0x70);
        bdst[i] = 32768u + sw;
        bsrc[i] = wrow + (size_t)row * VD + (j & 7) * 4;
    }

    auto issue_copies = [&](int c, uint32_t sbase) {
#pragma unroll
        for (int i = 0; i < 8; i++)
            CP_ASYNC16(sbase + adst[i], asrc[i] + c * KCH);
#pragma unroll
        for (int i = 0; i < 4; i++)
            CP_ASYNC16(sbase + bdst[i], bsrc[i] + c * KCH);
        CP_ASYNC_COMMIT();
    };

    issue_copies(0, stage_u32[0]);
    issue_copies(1, stage_u32[1]);

    if (tid < DD) {
        qsh[tid]  = g_q[b * DD + tid] + bv[tid];
        avsh[tid] = av[tid];
    }
    if (tid == 0) {
        MBARRIER_INIT(mbar0, 1);
        MBARRIER_INIT(mbar1, 1);
    }
    if (wid == 0) {
        TCGEN05_ALLOC(tptr_u32, 256);       // D0 @ +0, D1 @ +128
        TCGEN05_RELINQ();
    }
    __syncthreads();
    uint32_t tmem = s_tmem[0];

    const uint32_t idesc = (1u << 4) | (2u << 7) | (2u << 10)
                         | ((DD / 8) << 17) | (8u << 24);

    for (int c = 0; c < NCHUNK; c++) {
        int buf = c & 1;
        uint32_t mb = buf ? mbar1 : mbar0;
        uint32_t sbase = stage_u32[buf];
        if (c == NCHUNK - 1) CP_ASYNC_WAIT(0); else CP_ASYNC_WAIT(1);
        __syncthreads();
        if (wid == 0) {
            FENCE_PROXY_ASYNC();
            if (elect_one_pred()) {
                uint64_t a0 = make_desc(sbase);
                uint64_t a1 = make_desc(sbase + 16384);
                uint64_t b0 = make_desc(sbase + 32768);
#pragma unroll
                for (int s = 0; s < 4; s++) {
                    uint32_t en = (uint32_t)((c > 0) || (s > 0));
                    mma_tf32_ss(tmem,        a0 + s * 2, b0 + s * 2, idesc, en);
                    mma_tf32_ss(tmem + 128,  a1 + s * 2, b0 + s * 2, idesc, en);
                }
                TCGEN05_COMMIT(mb);
            }
        }
        if (c + 2 < NCHUNK) {
            MBARRIER_WAIT_PARITY(mb, (uint32_t)((c >> 1) & 1));
            issue_copies(c + 2, sbase);
        }
    }
    MBARRIER_WAIT_PARITY(mbar0, 1u);
    MBARRIER_WAIT_PARITY(mbar1, 1u);

    TCGEN05_FENCE_AFTER();

    // epilogue: warp w -> accumulator part=w>>2, subpartition w&3; LDTM pairs
    int part = wid >> 2;
    float s = 0.f;
#pragma unroll
    for (int gp = 0; gp < 2; gp++) {
        uint32_t dr0[32], dr1[32];
        TCGEN05_LD_X32(dr0, tmem + part * 128 + gp * 64);
        TCGEN05_LD_X32(dr1, tmem + part * 128 + gp * 64 + 32);
        TCGEN05_WAIT_LD();
#pragma unroll
        for (int j = 0; j < 32; j++) {
            int col = gp * 64 + j;
            s += avsh[col] * tanh_fast(qsh[col] + __uint_as_float(dr0[j]));
        }
#pragma unroll
        for (int j = 0; j < 32; j++) {
            int col = gp * 64 + 32 + j;
            s += avsh[col] * tanh_fast(qsh[col] + __uint_as_float(dr1[j]));
        }
    }
    int trow = part * 128 + (wid & 3) * 32 + lid;
    g_score[(size_t)b * TT + t0 + trow] = s + sbias[0];

    __syncthreads();
    if (wid == 0) TCGEN05_DEALLOC(tmem, 256);
    (void)Wv;

#else
    // ======== FFMA2 fallback (non-"a" compilation pass): two 128-row halves ====
    __shared__ __align__(16) float bsh[16][DD];
    __shared__ float vsh[16][128 + 1];

    int b  = blockIdx.y;
    int tid = threadIdx.x;
    int tx = tid & 15;
    int ty = tid >> 4;

    for (int half = 0; half < 2; half++) {
        int t0 = blockIdx.x * TILE_T + half * 128;

        unsigned long long acc[8][4];
#pragma unroll
        for (int i = 0; i < 8; i++)
#pragma unroll
            for (int j = 0; j < 4; j++) acc[i][j] = 0ull;

        const float* vptr = value + ((size_t)b * TT + t0) * VD;

        for (int kc = 0; kc < VD; kc += 16) {
            __syncthreads();
#pragma unroll
            for (int r = 0; r < 2; r++) {
                int idx = tid + r * 256;
                int row = idx >> 2;
                int k4  = (idx & 3) * 4;
                float4 vv = *(const float4*)(vptr + (size_t)row * VD + kc + k4);
                vsh[k4 + 0][row] = vv.x;
                vsh[k4 + 1][row] = vv.y;
                vsh[k4 + 2][row] = vv.z;
                vsh[k4 + 3][row] = vv.w;
            }
#pragma unroll
            for (int r = 0; r < 2; r++) {
                int idx = tid + r * 256;
                int kk  = idx >> 5;
                int d4  = (idx & 31) * 4;
                *(float4*)&bsh[kk][d4] = *(const float4*)(Wv + (size_t)(kc + kk) * DD + d4);
            }
            __syncthreads();

#pragma unroll
            for (int kk = 0; kk < 16; kk++) {
                unsigned long long ap[8];
#pragma unroll
                for (int i = 0; i < 8; i++) {
                    float a = vsh[kk][ty * 8 + i];
                    ap[i] = pack2(a, a);
                }
                unsigned long long bp[4];
#pragma unroll
                for (int j = 0; j < 4; j++)
                    bp[j] = *(const unsigned long long*)&bsh[kk][tx * 8 + j * 2];
#pragma unroll
                for (int i = 0; i < 8; i++)
#pragma unroll
                    for (int j = 0; j < 4; j++)
                        ffma2(acc[i][j], ap[i], bp[j]);
            }
        }

        float qv[8], avv[8];
#pragma unroll
        for (int j = 0; j < 8; j++) {
            int c = tx * 8 + j;
            qv[j]  = g_q[b * DD + c] + bv[c];
            avv[j] = av[c];
        }
        float part[8];
#pragma unroll
        for (int i = 0; i < 8; i++) {
            float s = 0.f;
#pragma unroll
            for (int j = 0; j < 4; j++) {
                float lo, hi;
                unpack2(acc[i][j], lo, hi);
                s += avv[2 * j]     * tanh_fast(qv[2 * j]     + lo);
                s += avv[2 * j + 1] * tanh_fast(qv[2 * j + 1] + hi);
            }
            part[i] = s;
        }
#pragma unroll
        for (int o = 8; o >= 1; o >>= 1)
#pragma unroll
            for (int i = 0; i < 8; i++)
                part[i] += __shfl_down_sync(0xffffffffu, part[i], o, 16);

        if (tx == 0) {
            float bias = *sbias;
#pragma unroll
            for (int i = 0; i < 8; i++)
                g_score[b * TT + t0 + ty * 8 + i] = part[i] + bias;
        }
        __syncthreads();
    }
#endif
}

// ---------------- kernel C: monotonic-attention scan ----------------
__device__ __forceinline__ float block_exscan512(float tsum, float* sh) {
    int lane = threadIdx.x & 31, wid = threadIdx.x >> 5;
    float x = tsum;
#pragma unroll
    for (int o = 1; o < 32; o <<= 1) {
        float y = __shfl_up_sync(0xffffffffu, x, o);
        if (lane >= o) x += y;
    }
    __syncthreads();
    if (lane == 31) sh[wid] = x;
    __syncthreads();
    if (wid == 0) {
        float v = (lane < 16) ? sh[lane] : 0.f;
        float xx = v;
#pragma unroll
        for (int o = 1; o < 32; o <<= 1) {
            float y = __shfl_up_sync(0xffffffffu, xx, o);
            if (lane >= o) xx += y;
        }
        if (lane < 16) sh[lane] = xx - v;
    }
    __syncthreads();
    return sh[wid] + (x - tsum);
}

__global__ __launch_bounds__(512) void scan_kernel(
    const float* __restrict__ prev, float* __restrict__ out_align) {
    __shared__ float sh[32];
    const float LOGTINY = -87.336544f;
    int b = blockIdx.x;
    int tid = threadIdx.x;
    int base = tid * 16;
    const float* sc = g_score + (size_t)b * TT;
    const float* pa = prev + (size_t)b * TT;

    float s[16], pv[16];
#pragma unroll
    for (int i = 0; i < 4; i++) {
        *(float4*)&s[i * 4]  = *(const float4*)(sc + base + i * 4);
        *(float4*)&pv[i * 4] = *(const float4*)(pa + base + i * 4);
    }

    float p[16], l[16];
#pragma unroll
    for (int i = 0; i < 16; i++) {
        float si = s[i];
        float e  = expf(-fabsf(si));
        float den = 1.f + e;
        p[i] = (si >= 0.f) ? (1.f / den) : (e / den);
        l[i] = fmaxf(-(fmaxf(si, 0.f) + log1pf(e)), LOGTINY);
    }

#pragma unroll
    for (int i = 1; i < 16; i++) l[i] += l[i - 1];
    float prefl = block_exscan512(l[15], sh);

    float cp[16];
#pragma unroll
    for (int i = 0; i < 16; i++) {
        cp[i] = expf(prefl + (i ? l[i - 1] : 0.f));
        pv[i] = pv[i] / fmaxf(cp[i], 1e-10f);
    }
#pragma unroll
    for (int i = 1; i < 16; i++) pv[i] += pv[i - 1];
    float prefu = block_exscan512(pv[15], sh);

    float asum = 0.f;
#pragma unroll
    for (int i = 0; i < 16; i++) {
        float al = p[i] * cp[i] * (prefu + pv[i]);
        s[i] = al;
        asum += al;
    }
#pragma unroll
    for (int i = 0; i < 4; i++)
        *(float4*)(out_align + (size_t)b * TT + base + i * 4) = *(float4*)&s[i * 4];

    float prefa = block_exscan512(asum, sh);
    if (tid == 511) g_sumA[b] = prefa + asum;
}

// ---------------- kernel D: partial S = alignment @ value (persistent, grid=148) ----------------
__global__ __launch_bounds__(512) void ctx_reduce_kernel(
    const float* __restrict__ value, const float* __restrict__ align) {
    __shared__ float ash[512];
    __shared__ float4 red[7][64];
    int tid = threadIdx.x;
    int k4 = tid & 63, tr = tid >> 6;       // 64 float4 cols x 8 t-offsets

    for (int w = blockIdx.x; w < 16 * BB; w += gridDim.x) {
        int b  = w >> 4;                    // 32 batches
        int tc = w & 15;                    // 16 chunks of 512 t
        int t0 = tc * 512;
        ash[tid] = align[(size_t)b * TT + t0 + tid];
        __syncthreads();
        const float4* vp = (const float4*)(value + ((size_t)b * TT + t0) * VD);
        float4 acc = make_float4(0.f, 0.f, 0.f, 0.f);
#pragma unroll 8
        for (int t = tr; t < 512; t += 8) {
            float a = ash[t];
            float4 v = vp[(size_t)t * 64 + k4];
            acc.x = fmaf(a, v.x, acc.x);
            acc.y = fmaf(a, v.y, acc.y);
            acc.z = fmaf(a, v.z, acc.z);
            acc.w = fmaf(a, v.w, acc.w);
        }
        if (tr) red[tr - 1][k4] = acc;
        __syncthreads();
        if (tr == 0) {
#pragma unroll
            for (int r = 0; r < 7; r++) {
                float4 rr = red[r][k4];
                acc.x += rr.x; acc.y += rr.y; acc.z += rr.z; acc.w += rr.w;
            }
            *(float4*)&g_Spart[tc][b][k4 * 4] = acc;
        }
        __syncthreads();                    // protect ash/red before next iteration
    }
}

// ---------------- kernel E: reduce partials + context = S @ Wv + sumA * bv ----------------
__global__ __launch_bounds__(256) void ctx_tail_kernel(
    const float* __restrict__ Wv, const float* __restrict__ bv,
    float* __restrict__ out_ctx) {
    __shared__ float Ssh[VD];
    __shared__ float half1[DD];
    int b = blockIdx.x;
    int tid = threadIdx.x;
    float s = 0.f;
#pragma unroll
    for (int c = 0; c < 16; c++) s += g_Spart[c][b][tid];
    Ssh[tid] = s;
    __syncthreads();
    int d = tid & 127, hf = tid >> 7;
    float acc = 0.f;
    const float* wv = Wv + (size_t)hf * 128 * DD + d;
#pragma unroll 8
    for (int k = 0; k < 128; k++)
        acc += Ssh[hf * 128 + k] * wv[(size_t)k * DD];
    if (hf) half1[d] = acc;
    __syncthreads();
    if (hf == 0)
        out_ctx[b * DD + d] = acc + half1[d] + g_sumA[b] * bv[d];
}

// ---------------- launcher ----------------
extern "C" void kernel_launch(void* const* d_in, const int* in_sizes, int n_in,
                              void* d_out, int out_size) {
    (void)in_sizes; (void)n_in; (void)out_size;
    const float* query = (const float*)d_in[0];
    const float* value = (const float*)d_in[1];
    const float* prev  = (const float*)d_in[2];
    const float* Wq    = (const float*)d_in[3];
    const float* bq    = (const float*)d_in[4];
    const float* Wv    = (const float*)d_in[5];
    const float* bv    = (const float*)d_in[6];
    const float* av    = (const float*)d_in[7];
    const float* sbias = (const float*)d_in[8];

    float* out       = (float*)d_out;
    float* out_ctx   = out;                  // [32, 128]
    float* out_align = out + BB * DD;        // [32, 8192]

    const int SCORE_DYN = 2 * STAGE_BYTES + 1024;
    cudaFuncSetAttribute(score_kernel, cudaFuncAttributeMaxDynamicSharedMemorySize, SCORE_DYN);

    setup_kernel<<<2 * BB + 1, 512>>>(query, Wq, bq, Wv);                          // launch 0
    score_kernel<<<dim3(TT / TILE_T, BB), 256, SCORE_DYN>>>(value, Wv, bv, av, sbias); // launch 1
    scan_kernel<<<BB, 512>>>(prev, out_align);                                     // launch 2
    ctx_reduce_kernel<<<148, 512>>>(value, out_align);                             // launch 3 -> ncu
    ctx_tail_kernel<<<BB, 256>>>(Wv, bv, out_ctx);                                 // launch 4
}

// round 17
// speedup vs baseline: 1.5744x; 1.5744x over previous
#include <cuda_runtime.h>
#include <cstdint>
#include <cstddef>

// Problem shapes (fixed)
#define BB   32
#define TT   8192
#define QD   512
#define VD   256
#define DD   128
#define TILE_T 256           // t-rows per score tile (2 x 128-row MMA accumulators)
#define KCH    32            // k-floats per SMEM chunk (= 128B = one SW128 atom row)
#define NCHUNK (VD / KCH)    // 8
#define STAGE_BYTES (3 * 16384)   // A0 + A1 + B per stage

#if defined(__CUDA_ARCH__) && (defined(__CUDA_ARCH_FEAT_SM103_ALL) || \
                               defined(__CUDA_ARCH_FEAT_SM100_ALL) || \
                               defined(__CUDA_ARCH_SPECIFIC__)     || \
                               defined(__CUDA_ARCH_FAMILY_SPECIFIC__))
#define HAS_TCGEN05 1
#else
#define HAS_TCGEN05 0
#endif

// ---------------- device scratch (no allocation allowed) ----------------
__device__ float g_q[BB * DD];
__device__ float g_WvT[DD * VD];        // Wv transposed: [d][k]
__device__ float g_score[BB * TT];
__device__ __align__(16) float g_Spart[32][BB][VD];
__device__ float g_sumA[BB];

// ---------------- generic PTX helpers ----------------
__device__ __forceinline__ uint32_t smem_u32(const void* p) {
    uint32_t a;
    asm("{ .reg .u64 t; cvta.to.shared.u64 t, %1; cvt.u32.u64 %0, t; }" : "=r"(a) : "l"(p));
    return a;
}
__device__ __forceinline__ uint32_t elect_one_pred() {
    uint32_t p;
    asm volatile("{\n\t.reg .pred p;\n\telect.sync _|p, 0xFFFFFFFF;\n\tselp.b32 %0, 1, 0, p;\n\t}" : "=r"(p));
    return p;
}
__device__ __forceinline__ float tanh_fast(float x) {
    float y;
    asm("tanh.approx.f32 %0, %1;" : "=f"(y) : "f"(x));
    return y;
}

#define CP_ASYNC16(dst_u32, src_ptr) \
    asm volatile("cp.async.cg.shared.global [%0], [%1], 16;" \
                 :: "r"(dst_u32), "l"(src_ptr) : "memory")
#define CP_ASYNC_COMMIT() asm volatile("cp.async.commit_group;" ::: "memory")
#define CP_ASYNC_WAIT(n)  asm volatile("cp.async.wait_group %0;" :: "n"(n) : "memory")

#define MBARRIER_INIT(addr, cnt) \
    asm volatile("mbarrier.init.shared.b64 [%0], %1;" :: "r"(addr), "r"(cnt) : "memory")

#define MBARRIER_WAIT_PARITY(mbar, parity) do {                                   \
    uint32_t _m = (mbar); uint32_t _p = (parity); uint32_t _d;                    \
    asm volatile("{\n\t.reg .pred p;\n\t"                                         \
        "mbarrier.try_wait.parity.acquire.cta.shared::cta.b64 p, [%1], %2;\n\t"   \
        "selp.b32 %0, 1, 0, p;\n\t}" : "=r"(_d) : "r"(_m), "r"(_p) : "memory");   \
    if (!_d) {                                                                    \
        asm volatile("{\n\t.reg .pred P1;\n\t"                                    \
            "WL_%=:\n\t"                                                          \
            "mbarrier.try_wait.parity.acquire.cta.shared::cta.b64 P1, [%0], %1, 0x989680;\n\t" \
            "@P1 bra.uni WD_%=;\n\t"                                              \
            "bra.uni WL_%=;\n\t"                                                  \
            "WD_%=:\n\t}" :: "r"(_m), "r"(_p) : "memory");                        \
    }                                                                             \
} while (0)

// ---------------- tcgen05 helpers ----------------
#define TCGEN05_ALLOC(res_addr, ncols) \
    asm volatile("tcgen05.alloc.cta_group::1.sync.aligned.shared::cta.b32 [%0], %1;" \
                 :: "r"(res_addr), "r"((uint32_t)(ncols)) : "memory")
#define TCGEN05_RELINQ() \
    asm volatile("tcgen05.relinquish_alloc_permit.cta_group::1.sync.aligned;")
#define TCGEN05_DEALLOC(tmem, ncols) \
    asm volatile("tcgen05.dealloc.cta_group::1.sync.aligned.b32 %0, %1;" :: "r"(tmem), "r"((uint32_t)(ncols)))
#define TCGEN05_COMMIT(mbar) \
    asm volatile("tcgen05.commit.cta_group::1.mbarrier::arrive::one.shared::cluster.b64 [%0];" \
                 :: "r"(mbar) : "memory")
#define TCGEN05_FENCE_AFTER() \
    asm volatile("tcgen05.fence::after_thread_sync;" ::: "memory")
#define TCGEN05_WAIT_LD() \
    asm volatile("tcgen05.wait::ld.sync.aligned;" ::: "memory")
#define FENCE_PROXY_ASYNC() \
    asm volatile("fence.proxy.async.shared::cta;" ::: "memory")

#define TCGEN05_LD_X32(r, tmem_addr)                                              \
    asm volatile("tcgen05.ld.sync.aligned.32x32b.x32.b32 "                        \
        "{%0, %1, %2, %3, %4, %5, %6, %7, "                                       \
        " %8, %9, %10, %11, %12, %13, %14, %15, "                                 \
        " %16, %17, %18, %19, %20, %21, %22, %23, "                               \
        " %24, %25, %26, %27, %28, %29, %30, %31}, [%32];"                        \
        : "=r"((r)[0]),  "=r"((r)[1]),  "=r"((r)[2]),  "=r"((r)[3]),              \
          "=r"((r)[4]),  "=r"((r)[5]),  "=r"((r)[6]),  "=r"((r)[7]),              \
          "=r"((r)[8]),  "=r"((r)[9]),  "=r"((r)[10]), "=r"((r)[11]),             \
          "=r"((r)[12]), "=r"((r)[13]), "=r"((r)[14]), "=r"((r)[15]),             \
          "=r"((r)[16]), "=r"((r)[17]), "=r"((r)[18]), "=r"((r)[19]),             \
          "=r"((r)[20]), "=r"((r)[21]), "=r"((r)[22]), "=r"((r)[23]),             \
          "=r"((r)[24]), "=r"((r)[25]), "=r"((r)[26]), "=r"((r)[27]),             \
          "=r"((r)[28]), "=r"((r)[29]), "=r"((r)[30]), "=r"((r)[31])              \
        : "r"(tmem_addr))

// SW128 K-major SMEM descriptor (LBO=1, SBO=64, version=1, layout=SW128)
static __device__ constexpr uint64_t SMEM_DESC_BASE_SW128 =
    (uint64_t(2) << 61) | (uint64_t(1) << 46) | (uint64_t(64) << 32) | (uint64_t(1) << 16);
__device__ __forceinline__ uint64_t make_desc(uint32_t addr) {
    return SMEM_DESC_BASE_SW128 | ((uint64_t)(addr >> 4) & 0x3FFF);
}

#if HAS_TCGEN05
__device__ __forceinline__ void mma_tf32_ss(uint32_t d_tmem, uint64_t a_desc, uint64_t b_desc,
                                            uint32_t idesc, uint32_t enable) {
    asm volatile(
        "{\n\t.reg .pred p;\n\t"
        "setp.ne.u32 p, %4, 0;\n\t"
        "tcgen05.mma.cta_group::1.kind::tf32 [%0], %1, %2, %3, {%5, %5, %5, %5}, p;\n\t}"
        :: "r"(d_tmem), "l"(a_desc), "l"(b_desc), "r"(idesc), "r"(enable), "r"(0u)
        : "memory");
}
#endif

// ---------------- f32x2 packed-FMA helpers (fallback path) ----------------
__device__ __forceinline__ unsigned long long pack2(float lo, float hi) {
    unsigned long long r;
    asm("mov.b64 %0, {%1, %2};" : "=l"(r) : "f"(lo), "f"(hi));
    return r;
}
__device__ __forceinline__ void unpack2(unsigned long long v, float& lo, float& hi) {
    asm("mov.b64 {%0, %1}, %2;" : "=f"(lo), "=f"(hi) : "l"(v));
}
__device__ __forceinline__ void ffma2(unsigned long long& d,
                                      unsigned long long a,
                                      unsigned long long b) {
    asm("fma.rn.f32x2 %0, %1, %2, %0;" : "+l"(d) : "l"(a), "l"(b));
}

// ---------------- merged setup: qproj (blocks 0-31) + WvT transpose (32-63) + zero (64) ----------------
__global__ __launch_bounds__(512) void setup_kernel(const float* __restrict__ query,
                                                    const float* __restrict__ Wq,
                                                    const float* __restrict__ bq,
                                                    const float* __restrict__ Wv) {
    __shared__ float part[4][DD];
    __shared__ float tile[32][33];
    int blk = blockIdx.x;
    int tid = threadIdx.x;

    if (blk < BB) {
        int b  = blk;
        int d  = tid & 127;
        int sl = tid >> 7;
        const float* qr = query + (size_t)b * QD + sl * 128;
        const float* wq = Wq + (size_t)sl * 128 * DD + d;
        float a0 = 0.f, a1 = 0.f, a2 = 0.f, a3 = 0.f;
#pragma unroll 8
        for (int k = 0; k < 128; k += 4) {
            a0 += qr[k + 0] * wq[(size_t)(k + 0) * DD];
            a1 += qr[k + 1] * wq[(size_t)(k + 1) * DD];
            a2 += qr[k + 2] * wq[(size_t)(k + 2) * DD];
            a3 += qr[k + 3] * wq[(size_t)(k + 3) * DD];
        }
        part[sl][d] = (a0 + a1) + (a2 + a3);
        __syncthreads();
        if (sl == 0)
            g_q[b * DD + d] = bq[d] + (part[0][d] + part[1][d]) + (part[2][d] + part[3][d]);
    } else if (blk < 2 * BB) {
        int idx = blk - BB;
        int k0 = (idx & 7) * 32;
        int d0 = (idx >> 3) * 32;
        int tx = tid & 31, ty = tid >> 5;
#pragma unroll
        for (int r = 0; r < 2; r++)
            tile[ty + r * 16][tx] = Wv[(size_t)(k0 + ty + r * 16) * DD + d0 + tx];
        __syncthreads();
#pragma unroll
        for (int r = 0; r < 2; r++)
            g_WvT[(size_t)(d0 + ty + r * 16) * VD + k0 + tx] = tile[tx][ty + r * 16];
    } else {
        if (tid < BB) g_sumA[tid] = 0.f;
    }
}

// ---------------- kernel B: score GEMM + Bahdanau epilogue (R10/R14 structure) ----------------
__global__ __launch_bounds__(256) void score_kernel(
    const float* __restrict__ value,
    const float* __restrict__ Wv,
    const float* __restrict__ bv,
    const float* __restrict__ av,
    const float* __restrict__ sbias) {

#if HAS_TCGEN05
    extern __shared__ char dynraw[];
    __shared__ uint32_t s_tmem[1];
    __shared__ __align__(8) unsigned long long s_mbar[2];
    __shared__ float qsh[DD], avsh[DD];

    char* dbase = (char*)(((uintptr_t)dynraw + 1023) & ~(uintptr_t)1023);

    int tid = threadIdx.x;
    int wid = tid >> 5, lid = tid & 31;
    int b = blockIdx.y, t0 = blockIdx.x * TILE_T;

    uint32_t mbar0 = smem_u32(&s_mbar[0]);
    uint32_t mbar1 = smem_u32(&s_mbar[1]);
    uint32_t tptr_u32 = smem_u32(&s_tmem[0]);
    uint32_t stage_u32[2] = { smem_u32(dbase), smem_u32(dbase + STAGE_BYTES) };

    const float* vrow = value + ((size_t)b * TT + t0) * VD;
    const float* wrow = g_WvT;

    // Per-thread copy slots: 8 A-slots (value rows 0..255) + 4 B-slots (WvT rows 0..127).
    uint32_t adst[8], bdst[4];
    const float* asrc[8];
    const float* bsrc[4];
#pragma unroll
    for (int i = 0; i < 8; i++) {
        int j = i * 256 + tid;
        int row = j >> 3;
        uint32_t off = (row & 127) * 128 + (j & 7) * 16;
        uint32_t sw = off ^ ((off >> 3) & 0x70);
        adst[i] = ((row >> 7) ? 16384u : 0u) + sw;
        asrc[i] = vrow + (size_t)row * VD + (j & 7) * 4;
    }
#pragma unroll
    for (int i = 0; i < 4; i++) {
        int j = i * 256 + tid;
        int row = j >> 3;
        uint32_t off = row * 128 + (j & 7) * 16;
        uint32_t sw = off ^ ((off >> 3) & 0x70);
        bdst[i] = 32768u + sw;
        bsrc[i] = wrow + (size_t)row * VD + (j & 7) * 4;
    }

    auto issue_copies = [&](int c, uint32_t sbase) {
#pragma unroll
        for (int i = 0; i < 8; i++)
            CP_ASYNC16(sbase + adst[i], asrc[i] + c * KCH);
#pragma unroll
        for (int i = 0; i < 4; i++)
            CP_ASYNC16(sbase + bdst[i], bsrc[i] + c * KCH);
        CP_ASYNC_COMMIT();
    };

    issue_copies(0, stage_u32[0]);
    issue_copies(1, stage_u32[1]);

    if (tid < DD) {
        qsh[tid]  = g_q[b * DD + tid] + bv[tid];
        avsh[tid] = av[tid];
    }
    if (tid == 0) {
        MBARRIER_INIT(mbar0, 1);
        MBARRIER_INIT(mbar1, 1);
    }
    if (wid == 0) {
        TCGEN05_ALLOC(tptr_u32, 256);       // D0 @ +0, D1 @ +128
        TCGEN05_RELINQ();
    }
    __syncthreads();
    uint32_t tmem = s_tmem[0];

    const uint32_t idesc = (1u << 4) | (2u << 7) | (2u << 10)
                         | ((DD / 8) << 17) | (8u << 24);

    for (int c = 0; c < NCHUNK; c++) {
        int buf = c & 1;
        uint32_t mb = buf ? mbar1 : mbar0;
        uint32_t sbase = stage_u32[buf];
        if (c == NCHUNK - 1) CP_ASYNC_WAIT(0); else CP_ASYNC_WAIT(1);
        __syncthreads();
        if (wid == 0) {
            FENCE_PROXY_ASYNC();
            if (elect_one_pred()) {
                uint64_t a0 = make_desc(sbase);
                uint64_t a1 = make_desc(sbase + 16384);
                uint64_t b0 = make_desc(sbase + 32768);
#pragma unroll
                for (int s = 0; s < 4; s++) {
                    uint32_t en = (uint32_t)((c > 0) || (s > 0));
                    mma_tf32_ss(tmem,        a0 + s * 2, b0 + s * 2, idesc, en);
                    mma_tf32_ss(tmem + 128,  a1 + s * 2, b0 + s * 2, idesc, en);
                }
                TCGEN05_COMMIT(mb);
            }
        }
        if (c + 2 < NCHUNK) {
            MBARRIER_WAIT_PARITY(mb, (uint32_t)((c >> 1) & 1));
            issue_copies(c + 2, sbase);
        }
    }
    MBARRIER_WAIT_PARITY(mbar0, 1u);
    MBARRIER_WAIT_PARITY(mbar1, 1u);

    TCGEN05_FENCE_AFTER();

    // epilogue: warp w -> accumulator part=w>>2, subpartition w&3; LDTM pairs
    int part = wid >> 2;
    float s = 0.f;
#pragma unroll
    for (int gp = 0; gp < 2; gp++) {
        uint32_t dr0[32], dr1[32];
        TCGEN05_LD_X32(dr0, tmem + part * 128 + gp * 64);
        TCGEN05_LD_X32(dr1, tmem + part * 128 + gp * 64 + 32);
        TCGEN05_WAIT_LD();
#pragma unroll
        for (int j = 0; j < 32; j++) {
            int col = gp * 64 + j;
            s += avsh[col] * tanh_fast(qsh[col] + __uint_as_float(dr0[j]));
        }
#pragma unroll
        for (int j = 0; j < 32; j++) {
            int col = gp * 64 + 32 + j;
            s += avsh[col] * tanh_fast(qsh[col] + __uint_as_float(dr1[j]));
        }
    }
    int trow = part * 128 + (wid & 3) * 32 + lid;
    g_score[(size_t)b * TT + t0 + trow] = s + sbias[0];

    __syncthreads();
    if (wid == 0) TCGEN05_DEALLOC(tmem, 256);
    (void)Wv;

#else
    // ======== FFMA2 fallback (non-"a" compilation pass): two 128-row halves ====
    __shared__ __align__(16) float bsh[16][DD];
    __shared__ float vsh[16][128 + 1];

    int b  = blockIdx.y;
    int tid = threadIdx.x;
    int tx = tid & 15;
    int ty = tid >> 4;

    for (int half = 0; half < 2; half++) {
        int t0 = blockIdx.x * TILE_T + half * 128;

        unsigned long long acc[8][4];
#pragma unroll
        for (int i = 0; i < 8; i++)
#pragma unroll
            for (int j = 0; j < 4; j++) acc[i][j] = 0ull;

        const float* vptr = value + ((size_t)b * TT + t0) * VD;

        for (int kc = 0; kc < VD; kc += 16) {
            __syncthreads();
#pragma unroll
            for (int r = 0; r < 2; r++) {
                int idx = tid + r * 256;
                int row = idx >> 2;
                int k4  = (idx & 3) * 4;
                float4 vv = *(const float4*)(vptr + (size_t)row * VD + kc + k4);
                vsh[k4 + 0][row] = vv.x;
                vsh[k4 + 1][row] = vv.y;
                vsh[k4 + 2][row] = vv.z;
                vsh[k4 + 3][row] = vv.w;
            }
#pragma unroll
            for (int r = 0; r < 2; r++) {
                int idx = tid + r * 256;
                int kk  = idx >> 5;
                int d4  = (idx & 31) * 4;
                *(float4*)&bsh[kk][d4] = *(const float4*)(Wv + (size_t)(kc + kk) * DD + d4);
            }
            __syncthreads();

#pragma unroll
            for (int kk = 0; kk < 16; kk++) {
                unsigned long long ap[8];
#pragma unroll
                for (int i = 0; i < 8; i++) {
                    float a = vsh[kk][ty * 8 + i];
                    ap[i] = pack2(a, a);
                }
                unsigned long long bp[4];
#pragma unroll
                for (int j = 0; j < 4; j++)
                    bp[j] = *(const unsigned long long*)&bsh[kk][tx * 8 + j * 2];
#pragma unroll
                for (int i = 0; i < 8; i++)
#pragma unroll
                    for (int j = 0; j < 4; j++)
                        ffma2(acc[i][j], ap[i], bp[j]);
            }
        }

        float qv[8], avv[8];
#pragma unroll
        for (int j = 0; j < 8; j++) {
            int c = tx * 8 + j;
            qv[j]  = g_q[b * DD + c] + bv[c];
            avv[j] = av[c];
        }
        float part[8];
#pragma unroll
        for (int i = 0; i < 8; i++) {
            float s = 0.f;
#pragma unroll
            for (int j = 0; j < 4; j++) {
                float lo, hi;
                unpack2(acc[i][j], lo, hi);
                s += avv[2 * j]     * tanh_fast(qv[2 * j]     + lo);
                s += avv[2 * j + 1] * tanh_fast(qv[2 * j + 1] + hi);
            }
            part[i] = s;
        }
#pragma unroll
        for (int o = 8; o >= 1; o >>= 1)
#pragma unroll
            for (int i = 0; i < 8; i++)
                part[i] += __shfl_down_sync(0xffffffffu, part[i], o, 16);

        if (tx == 0) {
            float bias = *sbias;
#pragma unroll
            for (int i = 0; i < 8; i++)
                g_score[b * TT + t0 + ty * 8 + i] = part[i] + bias;
        }
        __syncthreads();
    }
#endif
}

// ---------------- kernel C: monotonic-attention scan ----------------
__device__ __forceinline__ float block_exscan512(float tsum, float* sh) {
    int lane = threadIdx.x & 31, wid = threadIdx.x >> 5;
    float x = tsum;
#pragma unroll
    for (int o = 1; o < 32; o <<= 1) {
        float y = __shfl_up_sync(0xffffffffu, x, o);
        if (lane >= o) x += y;
    }
    __syncthreads();
    if (lane == 31) sh[wid] = x;
    __syncthreads();
    if (wid == 0) {
        float v = (lane < 16) ? sh[lane] : 0.f;
        float xx = v;
#pragma unroll
        for (int o = 1; o < 32; o <<= 1) {
            float y = __shfl_up_sync(0xffffffffu, xx, o);
            if (lane >= o) xx += y;
        }
        if (lane < 16) sh[lane] = xx - v;
    }
    __syncthreads();
    return sh[wid] + (x - tsum);
}

__global__ __launch_bounds__(512) void scan_kernel(
    const float* __restrict__ prev, float* __restrict__ out_align) {
    __shared__ float sh[32];
    const float LOGTINY = -87.336544f;
    int b = blockIdx.x;
    int tid = threadIdx.x;
    int base = tid * 16;
    const float* sc = g_score + (size_t)b * TT;
    const float* pa = prev + (size_t)b * TT;

    float s[16], pv[16];
#pragma unroll
    for (int i = 0; i < 4; i++) {
        *(float4*)&s[i * 4]  = *(const float4*)(sc + base + i * 4);
        *(float4*)&pv[i * 4] = *(const float4*)(pa + base + i * 4);
    }

    float p[16], l[16];
#pragma unroll
    for (int i = 0; i < 16; i++) {
        float si = s[i];
        float e  = expf(-fabsf(si));
        float den = 1.f + e;
        p[i] = (si >= 0.f) ? (1.f / den) : (e / den);
        l[i] = fmaxf(-(fmaxf(si, 0.f) + log1pf(e)), LOGTINY);
    }

#pragma unroll
    for (int i = 1; i < 16; i++) l[i] += l[i - 1];
    float prefl = block_exscan512(l[15], sh);

    float cp[16];
#pragma unroll
    for (int i = 0; i < 16; i++) {
        cp[i] = expf(prefl + (i ? l[i - 1] : 0.f));
        pv[i] = pv[i] / fmaxf(cp[i], 1e-10f);
    }
#pragma unroll
    for (int i = 1; i < 16; i++) pv[i] += pv[i - 1];
    float prefu = block_exscan512(pv[15], sh);

    float asum = 0.f;
#pragma unroll
    for (int i = 0; i < 16; i++) {
        float al = p[i] * cp[i] * (prefu + pv[i]);
        s[i] = al;
        asum += al;
    }
#pragma unroll
    for (int i = 0; i < 4; i++)
        *(float4*)(out_align + (size_t)b * TT + base + i * 4) = *(float4*)&s[i * 4];

    float prefa = block_exscan512(asum, sh);
    if (tid == 511) g_sumA[b] = prefa + asum;
}

// ---------------- kernel D: partial S = alignment @ value (R3 structure: 1024 blocks x 256 thr) ----------------
__global__ __launch_bounds__(256) void ctx_reduce_kernel(
    const float* __restrict__ value, const float* __restrict__ align) {
    __shared__ float ash[256];
    int tc = blockIdx.x;               // 32 t-chunks of 256
    int b  = blockIdx.y;
    int tid = threadIdx.x;
    int t0 = tc * 256;
    ash[tid] = align[(size_t)b * TT + t0 + tid];
    __syncthreads();
    const float* vp = value + ((size_t)b * TT + t0) * VD + tid;
    float acc = 0.f;
#pragma unroll 8
    for (int t = 0; t < 256; t++)
        acc += ash[t] * vp[(size_t)t * VD];
    g_Spart[tc][b][tid] = acc;         // plain store: deterministic
}

// ---------------- kernel E: reduce partials + context = S @ Wv + sumA * bv ----------------
__global__ __launch_bounds__(256) void ctx_tail_kernel(
    const float* __restrict__ Wv, const float* __restrict__ bv,
    float* __restrict__ out_ctx) {
    __shared__ float Ssh[VD];
    __shared__ float half1[DD];
    int b = blockIdx.x;
    int tid = threadIdx.x;
    float s = 0.f;
#pragma unroll
    for (int c = 0; c < 32; c++) s += g_Spart[c][b][tid];
    Ssh[tid] = s;
    __syncthreads();
    int d = tid & 127, hf = tid >> 7;
    float acc = 0.f;
    const float* wv = Wv + (size_t)hf * 128 * DD + d;
#pragma unroll 8
    for (int k = 0; k < 128; k++)
        acc += Ssh[hf * 128 + k] * wv[(size_t)k * DD];
    if (hf) half1[d] = acc;
    __syncthreads();
    if (hf == 0)
        out_ctx[b * DD + d] = acc + half1[d] + g_sumA[b] * bv[d];
}

// ---------------- launcher ----------------
extern "C" void kernel_launch(void* const* d_in, const int* in_sizes, int n_in,
                              void* d_out, int out_size) {
    (void)in_sizes; (void)n_in; (void)out_size;
    const float* query = (const float*)d_in[0];
    const float* value = (const float*)d_in[1];
    const float* prev  = (const float*)d_in[2];
    const float* Wq    = (const float*)d_in[3];
    const float* bq    = (const float*)d_in[4];
    const float* Wv    = (const float*)d_in[5];
    const float* bv    = (const float*)d_in[6];
    const float* av    = (const float*)d_in[7];
    const float* sbias = (const float*)d_in[8];

    float* out       = (float*)d_out;
    float* out_ctx   = out;                  // [32, 128]
    float* out_align = out + BB * DD;        // [32, 8192]

    const int SCORE_DYN = 2 * STAGE_BYTES + 1024;
    cudaFuncSetAttribute(score_kernel, cudaFuncAttributeMaxDynamicSharedMemorySize, SCORE_DYN);

    setup_kernel<<<2 * BB + 1, 512>>>(query, Wq, bq, Wv);                          // launch 0
    score_kernel<<<dim3(TT / TILE_T, BB), 256, SCORE_DYN>>>(value, Wv, bv, av, sbias); // launch 1
    scan_kernel<<<BB, 512>>>(prev, out_align);                                     // launch 2
    ctx_reduce_kernel<<<dim3(32, BB), 256>>>(value, out_align);                    // launch 3 -> ncu
    ctx_tail_kernel<<<BB, 256>>>(Wv, bv, out_ctx);                                 // launch 4
}